// round 14
// baseline (speedup 1.0000x reference)
#include <cuda_runtime.h>
#include <cstdint>

// BroadcastTC on GB300, round 14: fully DMA-fed pipeline.
// Inputs arrive via 2x cp.async.bulk (global->shared, mbarrier complete_tx);
// out1/out2 leave via cp.async.bulk (shared->global, bulk_group).
// Warps only do smem<->register compute. npairs = B*C = 1,048,576.
//   out1[xy,uv] = sum_k t1[xy*3+k]*t2[k*9+uv] / sqrt(3)   (81 floats)
//   out2[x,u]   = sum_kl t1[x*9+kl]*t2[kl*3+u] / 3        (9 floats)
//   out3        = dot(t1,t2) / sqrt(27)                   (1 float)
// Output layout: [out1 flat | out2 flat | out3 flat].
//
// Role split (warp-uniform): threads p (role 0) and p+128 (role 1) share pair p.

#define PPB 128
#define THREADS 256

__device__ __forceinline__ uint32_t smem_u32(const void* p) {
    uint32_t a;
    asm("{ .reg .u64 t; cvta.to.shared.u64 t, %1; cvt.u32.u64 %0, t; }"
        : "=r"(a) : "l"(p));
    return a;
}

__global__ __launch_bounds__(THREADS, 4)
void broadcast_tc_kernel(const float* __restrict__ T1,
                         const float* __restrict__ T2,
                         float* __restrict__ out,
                         int npairs)
{
    // s: inputs (t1 at [0..3455], t2 at [3456..6911]) then out1 staging.
    __shared__ __align__(16) float s[PPB * 81];    // 41472 B
    __shared__ __align__(16) float st2[PPB * 9];   // 4608 B (out2 staging)
    __shared__ float aux[PPB * 4];                 // 2048 B (role-0 partials)
    __shared__ __align__(8) unsigned long long mbar;

    const int tid  = threadIdx.x;
    const int p    = tid & (PPB - 1);
    const int role = tid >> 7;                     // warp-uniform
    const long long p0 = (long long)blockIdx.x * PPB;

    const uint32_t mb = smem_u32(&mbar);

    // ---- Phase 1: bulk-load inputs (2 x 13824 B) via async engine ----
    if (tid == 0) {
        asm volatile("mbarrier.init.shared.b64 [%0], 1;" :: "r"(mb) : "memory");
    }
    __syncthreads();   // init visible before expect_tx / waits
    if (tid == 0) {
        asm volatile("mbarrier.arrive.expect_tx.shared.b64 _, [%0], %1;"
                     :: "r"(mb), "r"((uint32_t)(2 * PPB * 27 * 4)) : "memory");
        asm volatile("cp.async.bulk.shared::cta.global.mbarrier::complete_tx::bytes"
                     " [%0], [%1], %2, [%3];"
                     :: "r"(smem_u32(s)), "l"(T1 + p0 * 27),
                        "r"((uint32_t)(PPB * 27 * 4)), "r"(mb) : "memory");
        asm volatile("cp.async.bulk.shared::cta.global.mbarrier::complete_tx::bytes"
                     " [%0], [%1], %2, [%3];"
                     :: "r"(smem_u32(s) + PPB * 27 * 4), "l"(T2 + p0 * 27),
                        "r"((uint32_t)(PPB * 27 * 4)), "r"(mb) : "memory");
    }
    // All threads wait for DMA completion (phase 0).
    {
        uint32_t done;
        asm volatile(
            "{\n\t"
            ".reg .pred P;\n\t"
            "WAIT_%=:\n\t"
            "mbarrier.try_wait.parity.acquire.cta.shared::cta.b64 P, [%1], 0, 0x989680;\n\t"
            "selp.b32 %0, 1, 0, P;\n\t"
            "@P bra.uni DONE_%=;\n\t"
            "bra.uni WAIT_%=;\n\t"
            "DONE_%=:\n\t"
            "}"
            : "=r"(done) : "r"(mb) : "memory");
    }

    // ---- Phase 2: per-role register gather (stride 27: conflict-free) ----
    float b[27], a[15];   // a[j] = t1[role*12 + j]
    #pragma unroll
    for (int j = 0; j < 27; j++) b[j] = s[PPB * 27 + p * 27 + j];
    {
        const int abase = p * 27 + role * 12;
        #pragma unroll
        for (int j = 0; j < 15; j++) a[j] = s[abase + j];
    }
    __syncthreads();   // B2: inputs consumed; s reusable for out1 staging

    const float n1 = 0.5773502691896258f;   // 1/sqrt(3)
    const float n2 = 0.3333333333333333f;   // 1/3
    const float n3 = 0.1924500897298753f;   // 1/sqrt(27)

    float d;   // out3 partial (both roles)

    if (role == 0) {
        // out1 rows xy = 0..3 -> s
        #pragma unroll
        for (int xy = 0; xy < 4; xy++) {
            const float c0 = a[xy * 3 + 0] * n1;
            const float c1 = a[xy * 3 + 1] * n1;
            const float c2 = a[xy * 3 + 2] * n1;
            #pragma unroll
            for (int uv = 0; uv < 9; uv++)
                s[p * 81 + xy * 9 + uv] = c0 * b[uv] + c1 * b[9 + uv] + c2 * b[18 + uv];
        }
        // out2 x=0 full -> st2 slots 0..2
        #pragma unroll
        for (int u = 0; u < 3; u++) {
            float r = 0.0f;
            #pragma unroll
            for (int kl = 0; kl < 9; kl++) r += a[kl] * b[kl * 3 + u];
            st2[p * 9 + u] = r * n2;
        }
        // out2 x=1 partial, kl=0..2 (t1[9..11]) -> aux
        #pragma unroll
        for (int u = 0; u < 3; u++)
            aux[p * 4 + u] = a[9] * b[u] + a[10] * b[3 + u] + a[11] * b[6 + u];
        // out3 partial j=0..11 -> aux
        d = 0.0f;
        #pragma unroll
        for (int j = 0; j < 12; j++) d += a[j] * b[j];
        aux[p * 4 + 3] = d;
    } else {
        // a[j] = t1[12+j]
        // out1 rows xy = 4..8 -> s
        #pragma unroll
        for (int xy = 4; xy < 9; xy++) {
            const float c0 = a[xy * 3 - 12] * n1;
            const float c1 = a[xy * 3 - 11] * n1;
            const float c2 = a[xy * 3 - 10] * n1;
            #pragma unroll
            for (int uv = 0; uv < 9; uv++)
                s[p * 81 + xy * 9 + uv] = c0 * b[uv] + c1 * b[9 + uv] + c2 * b[18 + uv];
        }
        // out2 x=2 full: t1[18+kl] = a[6+kl] -> st2 slots 6..8
        #pragma unroll
        for (int u = 0; u < 3; u++) {
            float r = 0.0f;
            #pragma unroll
            for (int kl = 0; kl < 9; kl++) r += a[6 + kl] * b[kl * 3 + u];
            st2[p * 9 + 6 + u] = r * n2;
        }
        // out3 partial j=12..26
        d = 0.0f;
        #pragma unroll
        for (int j = 0; j < 15; j++) d += a[j] * b[12 + j];
    }
    __syncthreads();   // B3: out1 fully staged; role-0 partials published

    // ---- Kick out1 bulk store (async engine, 41472 B) ----
    if (tid == 0) {
        asm volatile("fence.proxy.async.shared::cta;" ::: "memory");
        asm volatile("cp.async.bulk.global.shared::cta.bulk_group [%0], [%1], %2;"
                     :: "l"(out + p0 * 81), "r"(smem_u32(s)),
                        "r"((uint32_t)(PPB * 81 * 4)) : "memory");
        asm volatile("cp.async.bulk.commit_group;" ::: "memory");
    }

    if (role == 1) {
        // out2 x=1: combine partials -> st2 slots 3..5
        #pragma unroll
        for (int u = 0; u < 3; u++) {
            float r = aux[p * 4 + u];
            #pragma unroll
            for (int kl = 3; kl < 9; kl++) r += a[kl - 3] * b[kl * 3 + u];
            st2[p * 9 + 3 + u] = r * n2;
        }
        // out3: combine + coalesced streaming store (128 contiguous floats)
        __stcs(out + (long long)npairs * 90 + p0 + p, (d + aux[p * 4 + 3]) * n3);
    }
    __syncthreads();   // B4: st2 fully written

    // ---- out2 bulk store (4608 B), then drain both groups ----
    if (tid == 0) {
        asm volatile("fence.proxy.async.shared::cta;" ::: "memory");
        asm volatile("cp.async.bulk.global.shared::cta.bulk_group [%0], [%1], %2;"
                     :: "l"(out + (long long)npairs * 81 + p0 * 9),
                        "r"(smem_u32(st2)),
                        "r"((uint32_t)(PPB * 9 * 4)) : "memory");
        asm volatile("cp.async.bulk.commit_group;" ::: "memory");
        // smem must stay live until the engine has READ it.
        asm volatile("cp.async.bulk.wait_group.read 0;" ::: "memory");
        asm volatile("mbarrier.inval.shared.b64 [%0];" :: "r"(mb) : "memory");
    }
}

extern "C" void kernel_launch(void* const* d_in, const int* in_sizes, int n_in,
                              void* d_out, int out_size)
{
    const float* T1 = (const float*)d_in[0];
    const float* T2 = (const float*)d_in[1];
    float* out = (float*)d_out;

    const int npairs = in_sizes[0] / 27;     // 1,048,576
    const int grid = npairs / PPB;           // 8192

    broadcast_tc_kernel<<<grid, THREADS>>>(T1, T2, out, npairs);
}

// round 15
// speedup vs baseline: 1.1784x; 1.1784x over previous
#include <cuda_runtime.h>
#include <cstdint>

// BroadcastTC on GB300, round 15 (final structure): R12 pipeline with the
// late out2 bulk-DMA replaced by cheap per-warp float4 stores, so the only
// bulk wait at exit covers the long-since-issued out1 transfer.
// Inputs: per-thread cp.async (high read MLP). out1: cp.async.bulk store.
// npairs = B*C = 1,048,576; t1,t2 = 27 fp32 per pair.
//   out1[xy,uv] = sum_k t1[xy*3+k]*t2[k*9+uv] / sqrt(3)   (81 floats)
//   out2[x,u]   = sum_kl t1[x*9+kl]*t2[kl*3+u] / 3        (9 floats)
//   out3        = dot(t1,t2) / sqrt(27)                   (1 float)
// Output layout: [out1 flat | out2 flat | out3 flat].
//
// Role split (warp-uniform): threads p (role 0) and p+64 (role 1) share pair p.

#define PPB 64
#define THREADS 128

__device__ __forceinline__ uint32_t smem_u32(const void* p) {
    uint32_t a;
    asm("{ .reg .u64 t; cvta.to.shared.u64 t, %1; cvt.u32.u64 %0, t; }"
        : "=r"(a) : "l"(p));
    return a;
}

__global__ __launch_bounds__(THREADS, 8)
void broadcast_tc_kernel(const float* __restrict__ T1,
                         const float* __restrict__ T2,
                         float* __restrict__ out,
                         int npairs)
{
    // s: inputs (t1 at [0..1727], t2 at [1728..3455]) then out1 staging.
    __shared__ __align__(16) float s[PPB * 81];    // 20736 B
    __shared__ __align__(16) float st2[PPB * 9];   // 2304 B (out2 staging)
    __shared__ float aux[PPB * 4];                 // 1024 B (role-0 partials)

    const int tid  = threadIdx.x;
    const int p    = tid & (PPB - 1);
    const int role = tid >> 6;                     // warp-uniform
    const long long p0 = (long long)blockIdx.x * PPB;

    // ---- Phase 1: cp.async input staging (864 float4, L1-bypass) ----
    {
        const float4* g1 = (const float4*)(T1 + p0 * 27);   // 432 float4
        const float4* g2 = (const float4*)(T2 + p0 * 27);   // 432 float4
        const uint32_t sb = smem_u32(s);
        #pragma unroll
        for (int t = 0; t < 7; t++) {
            const int i = tid + t * THREADS;
            if (i < 864) {
                const float4* src = (i < 432) ? (g1 + i) : (g2 + (i - 432));
                asm volatile("cp.async.cg.shared.global [%0], [%1], 16;"
                             :: "r"(sb + i * 16), "l"(src) : "memory");
            }
        }
        asm volatile("cp.async.commit_group;" ::: "memory");
        asm volatile("cp.async.wait_group 0;" ::: "memory");
    }
    __syncthreads();   // B1: inputs visible

    // ---- Phase 2: per-role register gather (stride 27: conflict-free) ----
    float b[27], a[15];   // a[j] = t1[role*12 + j]
    #pragma unroll
    for (int j = 0; j < 27; j++) b[j] = s[PPB * 27 + p * 27 + j];
    {
        const int abase = p * 27 + role * 12;
        #pragma unroll
        for (int j = 0; j < 15; j++) a[j] = s[abase + j];
    }
    __syncthreads();   // B2: inputs consumed; s reusable for out1 staging

    const float n1 = 0.5773502691896258f;   // 1/sqrt(3)
    const float n2 = 0.3333333333333333f;   // 1/3
    const float n3 = 0.1924500897298753f;   // 1/sqrt(27)

    float d;   // out3 partial (both roles)

    if (role == 0) {
        // out1 rows xy = 0..3 -> s
        #pragma unroll
        for (int xy = 0; xy < 4; xy++) {
            const float c0 = a[xy * 3 + 0] * n1;
            const float c1 = a[xy * 3 + 1] * n1;
            const float c2 = a[xy * 3 + 2] * n1;
            #pragma unroll
            for (int uv = 0; uv < 9; uv++)
                s[p * 81 + xy * 9 + uv] = c0 * b[uv] + c1 * b[9 + uv] + c2 * b[18 + uv];
        }
        // out2 x=0 full -> st2 slots 0..2
        #pragma unroll
        for (int u = 0; u < 3; u++) {
            float r = 0.0f;
            #pragma unroll
            for (int kl = 0; kl < 9; kl++) r += a[kl] * b[kl * 3 + u];
            st2[p * 9 + u] = r * n2;
        }
        // out2 x=1 partial, kl=0..2 (t1[9..11]) -> aux
        #pragma unroll
        for (int u = 0; u < 3; u++)
            aux[p * 4 + u] = a[9] * b[u] + a[10] * b[3 + u] + a[11] * b[6 + u];
        // out3 partial j=0..11 -> aux
        d = 0.0f;
        #pragma unroll
        for (int j = 0; j < 12; j++) d += a[j] * b[j];
        aux[p * 4 + 3] = d;
    } else {
        // a[j] = t1[12+j]
        // out1 rows xy = 4..8 -> s
        #pragma unroll
        for (int xy = 4; xy < 9; xy++) {
            const float c0 = a[xy * 3 - 12] * n1;
            const float c1 = a[xy * 3 - 11] * n1;
            const float c2 = a[xy * 3 - 10] * n1;
            #pragma unroll
            for (int uv = 0; uv < 9; uv++)
                s[p * 81 + xy * 9 + uv] = c0 * b[uv] + c1 * b[9 + uv] + c2 * b[18 + uv];
        }
        // out2 x=2 full: t1[18+kl] = a[6+kl] -> st2 slots 6..8
        #pragma unroll
        for (int u = 0; u < 3; u++) {
            float r = 0.0f;
            #pragma unroll
            for (int kl = 0; kl < 9; kl++) r += a[6 + kl] * b[kl * 3 + u];
            st2[p * 9 + 6 + u] = r * n2;
        }
        // out3 partial j=12..26
        d = 0.0f;
        #pragma unroll
        for (int j = 0; j < 15; j++) d += a[j] * b[12 + j];
    }
    __syncthreads();   // B3: out1 fully staged; role-0 partials published

    // ---- Kick out1 bulk store immediately (async engine, 20736 B) ----
    if (tid == 0) {
        asm volatile("fence.proxy.async.shared::cta;" ::: "memory");
        asm volatile("cp.async.bulk.global.shared::cta.bulk_group [%0], [%1], %2;"
                     :: "l"(out + p0 * 81), "r"(smem_u32(s)),
                        "r"((uint32_t)(PPB * 81 * 4)) : "memory");
        asm volatile("cp.async.bulk.commit_group;" ::: "memory");
    }

    if (role == 1) {
        // out2 x=1: combine partials -> st2 slots 3..5
        #pragma unroll
        for (int u = 0; u < 3; u++) {
            float r = aux[p * 4 + u];
            #pragma unroll
            for (int kl = 3; kl < 9; kl++) r += a[kl - 3] * b[kl * 3 + u];
            st2[p * 9 + 3 + u] = r * n2;
        }
        // out3: combine + coalesced streaming store
        __stcs(out + (long long)npairs * 90 + p0 + p, (d + aux[p * 4 + 3]) * n3);
    }
    __syncthreads();   // B4: st2 fully written

    // ---- Copy out2 directly: 144 float4 per block (cheap, no DMA tail) ----
    {
        float4* o2 = (float4*)(out + (long long)npairs * 81 + p0 * 9);
        const float4* sv = (const float4*)st2;
        #pragma unroll
        for (int i = tid; i < PPB * 9 / 4; i += THREADS)
            __stcs(o2 + i, sv[i]);
    }

    // ---- Drain out1 bulk store (issued at B3 -> normally already done) ----
    if (tid == 0) {
        asm volatile("cp.async.bulk.wait_group.read 0;" ::: "memory");
    }
}

extern "C" void kernel_launch(void* const* d_in, const int* in_sizes, int n_in,
                              void* d_out, int out_size)
{
    const float* T1 = (const float*)d_in[0];
    const float* T2 = (const float*)d_in[1];
    float* out = (float*)d_out;

    const int npairs = in_sizes[0] / 27;     // 1,048,576
    const int grid = npairs / PPB;           // 16384

    broadcast_tc_kernel<<<grid, THREADS>>>(T1, T2, out, npairs);
}

// round 16
// speedup vs baseline: 1.1796x; 1.0010x over previous
#include <cuda_runtime.h>
#include <cstdint>

// BroadcastTC on GB300, round 16: R15 pipeline with __launch_bounds__(128,9)
// to cap regs at 56 and admit a 9th resident block per SM (smem 24KB x 9 =
// 216KB <= 228KB). Everything else identical to R15.
// npairs = B*C = 1,048,576; t1,t2 = 27 fp32 per pair.
//   out1[xy,uv] = sum_k t1[xy*3+k]*t2[k*9+uv] / sqrt(3)   (81 floats)
//   out2[x,u]   = sum_kl t1[x*9+kl]*t2[kl*3+u] / 3        (9 floats)
//   out3        = dot(t1,t2) / sqrt(27)                   (1 float)
// Output layout: [out1 flat | out2 flat | out3 flat].
//
// Role split (warp-uniform): threads p (role 0) and p+64 (role 1) share pair p.

#define PPB 64
#define THREADS 128

__device__ __forceinline__ uint32_t smem_u32(const void* p) {
    uint32_t a;
    asm("{ .reg .u64 t; cvta.to.shared.u64 t, %1; cvt.u32.u64 %0, t; }"
        : "=r"(a) : "l"(p));
    return a;
}

__global__ __launch_bounds__(THREADS, 9)
void broadcast_tc_kernel(const float* __restrict__ T1,
                         const float* __restrict__ T2,
                         float* __restrict__ out,
                         int npairs)
{
    // s: inputs (t1 at [0..1727], t2 at [1728..3455]) then out1 staging.
    __shared__ __align__(16) float s[PPB * 81];    // 20736 B
    __shared__ __align__(16) float st2[PPB * 9];   // 2304 B (out2 staging)
    __shared__ float aux[PPB * 4];                 // 1024 B (role-0 partials)

    const int tid  = threadIdx.x;
    const int p    = tid & (PPB - 1);
    const int role = tid >> 6;                     // warp-uniform
    const long long p0 = (long long)blockIdx.x * PPB;

    // ---- Phase 1: cp.async input staging (864 float4, L1-bypass) ----
    {
        const float4* g1 = (const float4*)(T1 + p0 * 27);   // 432 float4
        const float4* g2 = (const float4*)(T2 + p0 * 27);   // 432 float4
        const uint32_t sb = smem_u32(s);
        #pragma unroll
        for (int t = 0; t < 7; t++) {
            const int i = tid + t * THREADS;
            if (i < 864) {
                const float4* src = (i < 432) ? (g1 + i) : (g2 + (i - 432));
                asm volatile("cp.async.cg.shared.global [%0], [%1], 16;"
                             :: "r"(sb + i * 16), "l"(src) : "memory");
            }
        }
        asm volatile("cp.async.commit_group;" ::: "memory");
        asm volatile("cp.async.wait_group 0;" ::: "memory");
    }
    __syncthreads();   // B1: inputs visible

    // ---- Phase 2: per-role register gather (stride 27: conflict-free) ----
    float b[27], a[15];   // a[j] = t1[role*12 + j]
    #pragma unroll
    for (int j = 0; j < 27; j++) b[j] = s[PPB * 27 + p * 27 + j];
    {
        const int abase = p * 27 + role * 12;
        #pragma unroll
        for (int j = 0; j < 15; j++) a[j] = s[abase + j];
    }
    __syncthreads();   // B2: inputs consumed; s reusable for out1 staging

    const float n1 = 0.5773502691896258f;   // 1/sqrt(3)
    const float n2 = 0.3333333333333333f;   // 1/3
    const float n3 = 0.1924500897298753f;   // 1/sqrt(27)

    float d;   // out3 partial (both roles)

    if (role == 0) {
        // out1 rows xy = 0..3 -> s
        #pragma unroll
        for (int xy = 0; xy < 4; xy++) {
            const float c0 = a[xy * 3 + 0] * n1;
            const float c1 = a[xy * 3 + 1] * n1;
            const float c2 = a[xy * 3 + 2] * n1;
            #pragma unroll
            for (int uv = 0; uv < 9; uv++)
                s[p * 81 + xy * 9 + uv] = c0 * b[uv] + c1 * b[9 + uv] + c2 * b[18 + uv];
        }
        // out2 x=0 full -> st2 slots 0..2
        #pragma unroll
        for (int u = 0; u < 3; u++) {
            float r = 0.0f;
            #pragma unroll
            for (int kl = 0; kl < 9; kl++) r += a[kl] * b[kl * 3 + u];
            st2[p * 9 + u] = r * n2;
        }
        // out2 x=1 partial, kl=0..2 (t1[9..11]) -> aux
        #pragma unroll
        for (int u = 0; u < 3; u++)
            aux[p * 4 + u] = a[9] * b[u] + a[10] * b[3 + u] + a[11] * b[6 + u];
        // out3 partial j=0..11 -> aux
        d = 0.0f;
        #pragma unroll
        for (int j = 0; j < 12; j++) d += a[j] * b[j];
        aux[p * 4 + 3] = d;
    } else {
        // a[j] = t1[12+j]
        // out1 rows xy = 4..8 -> s
        #pragma unroll
        for (int xy = 4; xy < 9; xy++) {
            const float c0 = a[xy * 3 - 12] * n1;
            const float c1 = a[xy * 3 - 11] * n1;
            const float c2 = a[xy * 3 - 10] * n1;
            #pragma unroll
            for (int uv = 0; uv < 9; uv++)
                s[p * 81 + xy * 9 + uv] = c0 * b[uv] + c1 * b[9 + uv] + c2 * b[18 + uv];
        }
        // out2 x=2 full: t1[18+kl] = a[6+kl] -> st2 slots 6..8
        #pragma unroll
        for (int u = 0; u < 3; u++) {
            float r = 0.0f;
            #pragma unroll
            for (int kl = 0; kl < 9; kl++) r += a[6 + kl] * b[kl * 3 + u];
            st2[p * 9 + 6 + u] = r * n2;
        }
        // out3 partial j=12..26
        d = 0.0f;
        #pragma unroll
        for (int j = 0; j < 15; j++) d += a[j] * b[12 + j];
    }
    __syncthreads();   // B3: out1 fully staged; role-0 partials published

    // ---- Kick out1 bulk store immediately (async engine, 20736 B) ----
    if (tid == 0) {
        asm volatile("fence.proxy.async.shared::cta;" ::: "memory");
        asm volatile("cp.async.bulk.global.shared::cta.bulk_group [%0], [%1], %2;"
                     :: "l"(out + p0 * 81), "r"(smem_u32(s)),
                        "r"((uint32_t)(PPB * 81 * 4)) : "memory");
        asm volatile("cp.async.bulk.commit_group;" ::: "memory");
    }

    if (role == 1) {
        // out2 x=1: combine partials -> st2 slots 3..5
        #pragma unroll
        for (int u = 0; u < 3; u++) {
            float r = aux[p * 4 + u];
            #pragma unroll
            for (int kl = 3; kl < 9; kl++) r += a[kl - 3] * b[kl * 3 + u];
            st2[p * 9 + 3 + u] = r * n2;
        }
        // out3: combine + coalesced streaming store
        __stcs(out + (long long)npairs * 90 + p0 + p, (d + aux[p * 4 + 3]) * n3);
    }
    __syncthreads();   // B4: st2 fully written

    // ---- Copy out2 directly: 144 float4 per block ----
    {
        float4* o2 = (float4*)(out + (long long)npairs * 81 + p0 * 9);
        const float4* sv = (const float4*)st2;
        #pragma unroll
        for (int i = tid; i < PPB * 9 / 4; i += THREADS)
            __stcs(o2 + i, sv[i]);
    }

    // ---- Drain out1 bulk store (issued at B3 -> normally already done) ----
    if (tid == 0) {
        asm volatile("cp.async.bulk.wait_group.read 0;" ::: "memory");
    }
}

extern "C" void kernel_launch(void* const* d_in, const int* in_sizes, int n_in,
                              void* d_out, int out_size)
{
    const float* T1 = (const float*)d_in[0];
    const float* T2 = (const float*)d_in[1];
    float* out = (float*)d_out;

    const int npairs = in_sizes[0] / 27;     // 1,048,576
    const int grid = npairs / PPB;           // 16384

    broadcast_tc_kernel<<<grid, THREADS>>>(T1, T2, out, npairs);
}

// round 17
// speedup vs baseline: 1.1854x; 1.0049x over previous
#include <cuda_runtime.h>
#include <cstdint>

// BroadcastTC on GB300 — FINAL (round 16 structure, confirmed at ~93% of the
// LTS-fabric roofline; see session notes). npairs = B*C = 1,048,576;
// t1,t2 = 27 fp32 per pair.
//   out1[xy,uv] = sum_k t1[xy*3+k]*t2[k*9+uv] / sqrt(3)   (81 floats)
//   out2[x,u]   = sum_kl t1[x*9+kl]*t2[kl*3+u] / 3        (9 floats)
//   out3        = dot(t1,t2) / sqrt(27)                   (1 float)
// Output layout: [out1 flat | out2 flat | out3 flat].
//
// Structure: 64 pairs / 128 threads per block, 9 blocks/SM (regs capped 56).
//   - inputs: per-thread cp.async.cg (high read MLP, L1-bypass)
//   - compute: warp-uniform 2-role split (threads p / p+64 share pair p)
//   - out1: staged in smem, written by one cp.async.bulk (async engine)
//   - out2: staged in smem, per-warp float4 streaming stores
//   - out3: direct coalesced scalar streaming stores

#define PPB 64
#define THREADS 128

__device__ __forceinline__ uint32_t smem_u32(const void* p) {
    uint32_t a;
    asm("{ .reg .u64 t; cvta.to.shared.u64 t, %1; cvt.u32.u64 %0, t; }"
        : "=r"(a) : "l"(p));
    return a;
}

__global__ __launch_bounds__(THREADS, 9)
void broadcast_tc_kernel(const float* __restrict__ T1,
                         const float* __restrict__ T2,
                         float* __restrict__ out,
                         int npairs)
{
    // s: inputs (t1 at [0..1727], t2 at [1728..3455]) then out1 staging.
    __shared__ __align__(16) float s[PPB * 81];    // 20736 B
    __shared__ __align__(16) float st2[PPB * 9];   // 2304 B (out2 staging)
    __shared__ float aux[PPB * 4];                 // 1024 B (role-0 partials)

    const int tid  = threadIdx.x;
    const int p    = tid & (PPB - 1);
    const int role = tid >> 6;                     // warp-uniform
    const long long p0 = (long long)blockIdx.x * PPB;

    // ---- Phase 1: cp.async input staging (864 float4, L1-bypass) ----
    {
        const float4* g1 = (const float4*)(T1 + p0 * 27);   // 432 float4
        const float4* g2 = (const float4*)(T2 + p0 * 27);   // 432 float4
        const uint32_t sb = smem_u32(s);
        #pragma unroll
        for (int t = 0; t < 7; t++) {
            const int i = tid + t * THREADS;
            if (i < 864) {
                const float4* src = (i < 432) ? (g1 + i) : (g2 + (i - 432));
                asm volatile("cp.async.cg.shared.global [%0], [%1], 16;"
                             :: "r"(sb + i * 16), "l"(src) : "memory");
            }
        }
        asm volatile("cp.async.commit_group;" ::: "memory");
        asm volatile("cp.async.wait_group 0;" ::: "memory");
    }
    __syncthreads();   // B1: inputs visible

    // ---- Phase 2: per-role register gather (stride 27: conflict-free) ----
    float b[27], a[15];   // a[j] = t1[role*12 + j]
    #pragma unroll
    for (int j = 0; j < 27; j++) b[j] = s[PPB * 27 + p * 27 + j];
    {
        const int abase = p * 27 + role * 12;
        #pragma unroll
        for (int j = 0; j < 15; j++) a[j] = s[abase + j];
    }
    __syncthreads();   // B2: inputs consumed; s reusable for out1 staging

    const float n1 = 0.5773502691896258f;   // 1/sqrt(3)
    const float n2 = 0.3333333333333333f;   // 1/3
    const float n3 = 0.1924500897298753f;   // 1/sqrt(27)

    float d;   // out3 partial (both roles)

    if (role == 0) {
        // out1 rows xy = 0..3 -> s
        #pragma unroll
        for (int xy = 0; xy < 4; xy++) {
            const float c0 = a[xy * 3 + 0] * n1;
            const float c1 = a[xy * 3 + 1] * n1;
            const float c2 = a[xy * 3 + 2] * n1;
            #pragma unroll
            for (int uv = 0; uv < 9; uv++)
                s[p * 81 + xy * 9 + uv] = c0 * b[uv] + c1 * b[9 + uv] + c2 * b[18 + uv];
        }
        // out2 x=0 full -> st2 slots 0..2
        #pragma unroll
        for (int u = 0; u < 3; u++) {
            float r = 0.0f;
            #pragma unroll
            for (int kl = 0; kl < 9; kl++) r += a[kl] * b[kl * 3 + u];
            st2[p * 9 + u] = r * n2;
        }
        // out2 x=1 partial, kl=0..2 (t1[9..11]) -> aux
        #pragma unroll
        for (int u = 0; u < 3; u++)
            aux[p * 4 + u] = a[9] * b[u] + a[10] * b[3 + u] + a[11] * b[6 + u];
        // out3 partial j=0..11 -> aux
        d = 0.0f;
        #pragma unroll
        for (int j = 0; j < 12; j++) d += a[j] * b[j];
        aux[p * 4 + 3] = d;
    } else {
        // a[j] = t1[12+j]
        // out1 rows xy = 4..8 -> s
        #pragma unroll
        for (int xy = 4; xy < 9; xy++) {
            const float c0 = a[xy * 3 - 12] * n1;
            const float c1 = a[xy * 3 - 11] * n1;
            const float c2 = a[xy * 3 - 10] * n1;
            #pragma unroll
            for (int uv = 0; uv < 9; uv++)
                s[p * 81 + xy * 9 + uv] = c0 * b[uv] + c1 * b[9 + uv] + c2 * b[18 + uv];
        }
        // out2 x=2 full: t1[18+kl] = a[6+kl] -> st2 slots 6..8
        #pragma unroll
        for (int u = 0; u < 3; u++) {
            float r = 0.0f;
            #pragma unroll
            for (int kl = 0; kl < 9; kl++) r += a[6 + kl] * b[kl * 3 + u];
            st2[p * 9 + 6 + u] = r * n2;
        }
        // out3 partial j=12..26
        d = 0.0f;
        #pragma unroll
        for (int j = 0; j < 15; j++) d += a[j] * b[12 + j];
    }
    __syncthreads();   // B3: out1 fully staged; role-0 partials published

    // ---- Kick out1 bulk store immediately (async engine, 20736 B) ----
    if (tid == 0) {
        asm volatile("fence.proxy.async.shared::cta;" ::: "memory");
        asm volatile("cp.async.bulk.global.shared::cta.bulk_group [%0], [%1], %2;"
                     :: "l"(out + p0 * 81), "r"(smem_u32(s)),
                        "r"((uint32_t)(PPB * 81 * 4)) : "memory");
        asm volatile("cp.async.bulk.commit_group;" ::: "memory");
    }

    if (role == 1) {
        // out2 x=1: combine partials -> st2 slots 3..5
        #pragma unroll
        for (int u = 0; u < 3; u++) {
            float r = aux[p * 4 + u];
            #pragma unroll
            for (int kl = 3; kl < 9; kl++) r += a[kl - 3] * b[kl * 3 + u];
            st2[p * 9 + 3 + u] = r * n2;
        }
        // out3: combine + coalesced streaming store
        __stcs(out + (long long)npairs * 90 + p0 + p, (d + aux[p * 4 + 3]) * n3);
    }
    __syncthreads();   // B4: st2 fully written

    // ---- Copy out2 directly: 144 float4 per block ----
    {
        float4* o2 = (float4*)(out + (long long)npairs * 81 + p0 * 9);
        const float4* sv = (const float4*)st2;
        #pragma unroll
        for (int i = tid; i < PPB * 9 / 4; i += THREADS)
            __stcs(o2 + i, sv[i]);
    }

    // ---- Drain out1 bulk store (issued at B3 -> normally already done) ----
    if (tid == 0) {
        asm volatile("cp.async.bulk.wait_group.read 0;" ::: "memory");
    }
}

extern "C" void kernel_launch(void* const* d_in, const int* in_sizes, int n_in,
                              void* d_out, int out_size)
{
    const float* T1 = (const float*)d_in[0];
    const float* T2 = (const float*)d_in[1];
    float* out = (float*)d_out;

    const int npairs = in_sizes[0] / 27;     // 1,048,576
    const int grid = npairs / PPB;           // 16384

    broadcast_tc_kernel<<<grid, THREADS>>>(T1, T2, out, npairs);
}